// round 15
// baseline (speedup 1.0000x reference)
#include <cuda_runtime.h>
#include <cuda_fp16.h>
#include <cstdint>

#define NSP 100000
#define NRX 200000
#define NED 1000000
#define DM  128
#define BGR 50
#define NS_PER 2000
#define NR_PER 4000
#define CAP_R 32        // per-reaction list capacity (deg lambda = 5)
#define CAP_S 64        // per-species list capacity (deg lambda = 10)

// State buffers — all fp16
__device__ __half g_hsA[NSP * DM];
__device__ __half g_hsB[NSP * DM];
__device__ __half g_hrA[NRX * DM];
__device__ __half g_hrB[NRX * DM];
// Pre-transposed fp16 weights: [which of 4][n=128][k=256]
__device__ __half g_wt[4][128 * 256];
// Adjacency (built per launch)
__device__ int g_cntR[NRX];
__device__ int g_cntS[NSP];
__device__ int g_idxR[(size_t)NRX * CAP_R];
__device__ int g_idxS[(size_t)NSP * CAP_S];

// ---------------------------------------------------------------------------
__device__ __forceinline__ uint32_t smem_u32(const void* p) {
    uint32_t a;
    asm("{ .reg .u64 t; cvta.to.shared.u64 t, %1; cvt.u32.u64 %0, t; }" : "=r"(a) : "l"(p));
    return a;
}
__device__ __forceinline__ void ldsm4(uint32_t r[4], uint32_t addr) {
    asm volatile("ldmatrix.sync.aligned.m8n8.x4.shared.b16 {%0,%1,%2,%3}, [%4];"
                 : "=r"(r[0]), "=r"(r[1]), "=r"(r[2]), "=r"(r[3]) : "r"(addr));
}
__device__ __forceinline__ void mma16816(float c[4], const uint32_t a[4],
                                         uint32_t b0, uint32_t b1) {
    asm volatile(
        "mma.sync.aligned.m16n8k16.row.col.f32.f16.f16.f32 "
        "{%0,%1,%2,%3}, {%4,%5,%6,%7}, {%8,%9}, {%0,%1,%2,%3};"
        : "+f"(c[0]), "+f"(c[1]), "+f"(c[2]), "+f"(c[3])
        : "r"(a[0]), "r"(a[1]), "r"(a[2]), "r"(a[3]), "r"(b0), "r"(b1));
}
__device__ __forceinline__ void cpa16(uint32_t smem, const void* gmem, uint32_t bytes) {
    asm volatile("cp.async.ca.shared.global [%0], [%1], 16, %2;"
                 :: "r"(smem), "l"(gmem), "r"(bytes) : "memory");
}
__device__ __forceinline__ void red8(__half* p, uint2 v) {
    asm volatile("red.global.add.noftz.v2.f16x2 [%0], {%1, %2};"
                 :: "l"(p), "r"(v.x), "r"(v.y) : "memory");
}

// ---------------------------------------------------------------------------
// Adjacency build: one pass over edges, slot placement via atomicAdd.
__global__ void k_build(const int* __restrict__ es, const int* __restrict__ ed) {
    int e = blockIdx.x * blockDim.x + threadIdx.x;
    if (e >= NED) return;
    int s = es[e], d = ed[e];
    int slotS = atomicAdd(&g_cntS[s], 1);
    if (slotS < CAP_S) g_idxS[(size_t)s * CAP_S + slotS] = d;
    int slotR = atomicAdd(&g_cntR[d], 1);
    if (slotR < CAP_R) g_idxR[(size_t)d * CAP_R + slotR] = s;
}

// ---------------------------------------------------------------------------
// Fused init + weight prep.
#define IBS ((NSP * 32 + 255) / 256)
#define IBR ((NRX * 32 + 255) / 256)
__global__ void k_init(const int* __restrict__ sidx, const int* __restrict__ ext,
                       const float* __restrict__ st, const float* __restrict__ et,
                       const int* __restrict__ tids, const float* __restrict__ params,
                       const float* __restrict__ tt, const float* __restrict__ Wp,
                       const float* __restrict__ bp,
                       const float* __restrict__ Wr, const float* __restrict__ Ws,
                       __half* __restrict__ hs, __half* __restrict__ hr) {
    if ((int)blockIdx.x < IBS) {
        int t = blockIdx.x * blockDim.x + threadIdx.x;
        int row = t >> 5, c = t & 31;
        if (row >= NSP) return;
        int si = sidx[row], ei = ext[row];
        float4 a = ((const float4*)st)[si * 32 + c];
        float4 b = ((const float4*)et)[ei * 32 + c];
        __half2 o01 = __floats2half2_rn(a.x + b.x, a.y + b.y);
        __half2 o23 = __floats2half2_rn(a.z + b.z, a.w + b.w);
        uint2 o;
        o.x = *(uint32_t*)&o01; o.y = *(uint32_t*)&o23;
        ((uint2*)hs)[row * 32 + c] = o;
    } else if ((int)blockIdx.x < IBS + IBR) {
        int t = ((int)blockIdx.x - IBS) * blockDim.x + threadIdx.x;
        int row = t >> 5, c = t & 31;
        if (row >= NRX) return;
        int ti = tids[row];
        float4 acc = ((const float4*)tt)[ti * 32 + c];
        float4 bb  = ((const float4*)bp)[c];
        acc.x += bb.x; acc.y += bb.y; acc.z += bb.z; acc.w += bb.w;
#pragma unroll
        for (int k = 0; k < 8; k++) {
            float p = params[row * 8 + k];
            float4 w = ((const float4*)Wp)[k * 32 + c];
            acc.x += p * w.x; acc.y += p * w.y; acc.z += p * w.z; acc.w += p * w.w;
        }
        __half2 o01 = __floats2half2_rn(acc.x, acc.y);
        __half2 o23 = __floats2half2_rn(acc.z, acc.w);
        uint2 o;
        o.x = *(uint32_t*)&o01; o.y = *(uint32_t*)&o23;
        ((uint2*)hr)[row * 32 + c] = o;
    } else {
        int idx = ((int)blockIdx.x - IBS - IBR) * blockDim.x + threadIdx.x;
        if (idx >= 4 * 256 * 128) return;
        int l = idx >> 15;
        int rem = idx & 32767;
        int k = rem >> 7, n = rem & 127;
        const float* src = (l & 1) ? (Ws + (size_t)(l >> 1) * 2 * DM * DM)
                                   : (Wr + (size_t)(l >> 1) * 2 * DM * DM);
        g_wt[l][n * 256 + k] = __float2half(src[k * DM + n]);
    }
}

// ---------------------------------------------------------------------------
// Persistent fused GEMM + scatter. 512 threads, warp tile 32x32, B-frags
// hoisted to registers (R14-proven). Destination is ZEROED before launch;
// both jobs accumulate additively via 8B f16x2 REDs (order-free):
//   job A (message): per src row, scatter acc row to all dst rows in its list
//   job B (state):   RED (acc + bias) into its own dst row
#define PITCH2 136
#define PB2    (PITCH2 * 2)
#define TILE2  (128 * PB2)         // 34816 B
#define GEMM_GRID 148
#define GEMM_SMEM (4 * TILE2)      // W + X0 + X1 + epi staging

__global__ void __launch_bounds__(512, 1) k_gemm_fused(
    const __half* __restrict__ XA, const __half* __restrict__ WtA,
    int nA, int koffA, int reluA,
    const int* __restrict__ cntA, const int* __restrict__ idxA, int capA,
    __half* __restrict__ dstA,
    const __half* __restrict__ XB, const __half* __restrict__ WtB,
    int nB, int koffB, int reluB,
    const float* __restrict__ biasB, __half* __restrict__ dstB)
{
    extern __shared__ char sm[];
    uint32_t aW  = smem_u32(sm);
    uint32_t aX0 = aW + TILE2;
    uint32_t aX1 = aX0 + TILE2;
    char* epi = sm + 3 * TILE2;

    int G = gridDim.x;
    int tA = (nA + 127) >> 7, tB = (nB + 127) >> 7;
    int cA = (int)(((long long)G * tA) / (tA + tB));
    if (tA > 0 && cA == 0) cA = 1;
    if (tB > 0 && cA == G) cA = G - 1;

    const bool jobB = ((int)blockIdx.x >= cA);
    const __half* X  = jobB ? XB : XA;
    const __half* Wt = jobB ? WtB : WtA;
    const int n      = jobB ? nB : nA;
    const int koff   = jobB ? koffB : koffA;
    const int relu   = jobB ? reluB : reluA;
    const int nT     = jobB ? tB : tA;
    const int tile0  = jobB ? ((int)blockIdx.x - cA) : (int)blockIdx.x;
    const int stride = jobB ? (G - cA) : cA;

    int tid = threadIdx.x;
    int lane = tid & 31, wid = tid >> 5;
    int wm = (wid & 3) * 32;
    int wn = (wid >> 2) * 32;

    // ---- W tile -> smem (one-time) ----
#pragma unroll
    for (int i = 0; i < 4; i++) {
        int f = i * 512 + tid;
        int r = f >> 4, c = f & 15;
        cpa16(aW + (uint32_t)r * PB2 + c * 16,
              Wt + (size_t)r * 256 + koff + c * 8, 16u);
    }
    asm volatile("cp.async.commit_group;" ::: "memory");

    bool active = (tile0 < nT);

    if (active) {
        int rb = tile0 * 128;
#pragma unroll
        for (int i = 0; i < 4; i++) {
            int f = i * 512 + tid;
            int r = f >> 4, c = f & 15;
            int gr = rb + r;
            const __half* gp = X + (size_t)(gr < n ? gr : 0) * DM + c * 8;
            cpa16(aX0 + (uint32_t)r * PB2 + c * 16, gp, (gr < n) ? 16u : 0u);
        }
    }
    asm volatile("cp.async.commit_group;" ::: "memory");
    asm volatile("cp.async.wait_group 1;" ::: "memory");
    __syncthreads();

    // ---- hoist B fragments ----
    uint32_t bOff = (uint32_t)(wn + (lane & 7) + ((lane >> 4) & 1) * 8) * PB2
                  + (((lane >> 3) & 1) * 8) * 2;
    uint32_t bF[8][8];
#pragma unroll
    for (int ks = 0; ks < 8; ks++)
#pragma unroll
        for (int q = 0; q < 2; q++)
            ldsm4(&bF[ks][q * 4], aW + bOff + ks * 32 + q * 16 * PB2);

    if (!active) {
        asm volatile("cp.async.wait_group 0;" ::: "memory");
        return;
    }

    uint32_t aOff = (uint32_t)(wm + (lane & 15)) * PB2 + ((lane >> 4) * 8) * 2;
    const __half2 z2 = __float2half2_rn(0.f);

    int t = tile0, buf = 0;
    while (t < nT) {
        int tn = t + stride;
        if (tn < nT) {
            uint32_t aXn = buf ? aX0 : aX1;
            int rb = tn * 128;
#pragma unroll
            for (int i = 0; i < 4; i++) {
                int f = i * 512 + tid;
                int r = f >> 4, c = f & 15;
                int gr = rb + r;
                const __half* gp = X + (size_t)(gr < n ? gr : 0) * DM + c * 8;
                cpa16(aXn + (uint32_t)r * PB2 + c * 16, gp, (gr < n) ? 16u : 0u);
            }
            asm volatile("cp.async.commit_group;" ::: "memory");
            asm volatile("cp.async.wait_group 1;" ::: "memory");
        } else {
            asm volatile("cp.async.wait_group 0;" ::: "memory");
        }
        __syncthreads();

        uint32_t aX = buf ? aX1 : aX0;
        float acc[2][4][4];
#pragma unroll
        for (int mt = 0; mt < 2; mt++)
#pragma unroll
            for (int nt = 0; nt < 4; nt++)
#pragma unroll
                for (int j = 0; j < 4; j++) acc[mt][nt][j] = 0.f;

#pragma unroll
        for (int ks = 0; ks < 8; ks++) {
            uint32_t aF[2][4];
            ldsm4(aF[0], aX + aOff + ks * 32);
            ldsm4(aF[1], aX + aOff + ks * 32 + 16 * PB2);
            if (relu) {
#pragma unroll
                for (int mt = 0; mt < 2; mt++)
#pragma unroll
                    for (int j = 0; j < 4; j++) {
                        __half2 h = __hmax2(*(__half2*)&aF[mt][j], z2);
                        aF[mt][j] = *(uint32_t*)&h;
                    }
            }
#pragma unroll
            for (int mt = 0; mt < 2; mt++)
#pragma unroll
                for (int q = 0; q < 2; q++) {
                    mma16816(acc[mt][q * 2 + 0], aF[mt], bF[ks][q * 4 + 0], bF[ks][q * 4 + 1]);
                    mma16816(acc[mt][q * 2 + 1], aF[mt], bF[ks][q * 4 + 2], bF[ks][q * 4 + 3]);
                }
        }

        // ---- epilogue: stage tile in smem, then RED-scatter ----
        int r0 = (lane >> 2);
        int c0 = (lane & 3) * 2;
#pragma unroll
        for (int mt = 0; mt < 2; mt++) {
#pragma unroll
            for (int nt = 0; nt < 4; nt++) {
                int col = wn + nt * 8 + c0;
                float2 b2 = make_float2(0.f, 0.f);
                if (jobB) b2 = *(const float2*)&biasB[col];
                int rA = wm + mt * 16 + r0;
                int rB = rA + 8;
                *(__half2*)(epi + (uint32_t)rA * PB2 + col * 2) =
                    __floats2half2_rn(acc[mt][nt][0] + b2.x, acc[mt][nt][1] + b2.y);
                *(__half2*)(epi + (uint32_t)rB * PB2 + col * 2) =
                    __floats2half2_rn(acc[mt][nt][2] + b2.x, acc[mt][nt][3] + b2.y);
            }
        }
        __syncthreads();

        int rowBase = t * 128;
#pragma unroll 1
        for (int rr = 0; rr < 8; rr++) {
            int r = wid * 8 + rr;
            int grow = rowBase + r;
            if (grow >= n) continue;
            uint2 v = *(uint2*)(epi + (uint32_t)r * PB2 + lane * 8);
            if (!jobB) {
                int deg = cntA[grow];
                if (deg > capA) deg = capA;
                const int* lst = idxA + (size_t)grow * capA;
                for (int i = 0; i < deg; i++)
                    red8(dstA + (size_t)lst[i] * DM + lane * 4, v);
            } else {
                red8(dstB + (size_t)grow * DM + lane * 4, v);
            }
        }
        __syncthreads();   // epi + aX reuse
        t = tn;
        buf ^= 1;
    }
}

// ---------------------------------------------------------------------------
// Pool: fp16 states, relu on load, fp32 accumulation.
__global__ void k_pool(const __half* __restrict__ hs, const __half* __restrict__ hr,
                       float* __restrict__ out) {
    int kind = blockIdx.z;
    int b = blockIdx.y;
    int lane = threadIdx.x & 31;
    int g = threadIdx.x >> 5;
    int col2 = blockIdx.x * 32 + lane;
    const __half* h = kind ? hr : hs;
    int np = kind ? NR_PER : NS_PER;
    float inv = kind ? (1.f / NR_PER) : (1.f / NS_PER);
    size_t base2 = (size_t)b * np * 64;
    const __half2* h2 = (const __half2*)h;
    float sx = 0.f, sy = 0.f;
    for (int i = g; i < np; i += 8) {
        float2 f = __half22float2(h2[base2 + (size_t)i * 64 + col2]);
        sx += fmaxf(f.x, 0.f);
        sy += fmaxf(f.y, 0.f);
    }
    __shared__ float red[8][64];
    red[g][lane * 2]     = sx;
    red[g][lane * 2 + 1] = sy;
    __syncthreads();
    if (g == 0) {
        float tx = 0.f, ty = 0.f;
#pragma unroll
        for (int j = 0; j < 8; j++) { tx += red[j][lane * 2]; ty += red[j][lane * 2 + 1]; }
        int col = col2 * 2;
        out[b * 256 + kind * 128 + col]     = tx * inv;
        out[b * 256 + kind * 128 + col + 1] = ty * inv;
    }
}

// ---------------------------------------------------------------------------
extern "C" void kernel_launch(void* const* d_in, const int* in_sizes, int n_in,
                              void* d_out, int out_size) {
    const int*   species_indices = (const int*)  d_in[0];
    const int*   is_external     = (const int*)  d_in[1];
    const int*   prop_type_ids   = (const int*)  d_in[2];
    const float* prop_params     = (const float*)d_in[3];
    const int*   edge_species    = (const int*)  d_in[4];
    const int*   edge_reaction   = (const int*)  d_in[5];
    const float* species_table   = (const float*)d_in[8];
    const float* external_table  = (const float*)d_in[9];
    const float* type_table      = (const float*)d_in[10];
    const float* W_param         = (const float*)d_in[11];
    const float* b_param         = (const float*)d_in[12];
    const float* Wr              = (const float*)d_in[13];
    const float* br              = (const float*)d_in[14];
    const float* Ws              = (const float*)d_in[15];
    const float* bs              = (const float*)d_in[16];
    float* out = (float*)d_out;

    __half *hsA, *hsB, *hrA, *hrB, *wt;
    int *cntR, *cntS, *idxR, *idxS;
    cudaGetSymbolAddress((void**)&hsA, g_hsA);
    cudaGetSymbolAddress((void**)&hsB, g_hsB);
    cudaGetSymbolAddress((void**)&hrA, g_hrA);
    cudaGetSymbolAddress((void**)&hrB, g_hrB);
    cudaGetSymbolAddress((void**)&wt, g_wt);
    cudaGetSymbolAddress((void**)&cntR, g_cntR);
    cudaGetSymbolAddress((void**)&cntS, g_cntS);
    cudaGetSymbolAddress((void**)&idxR, g_idxR);
    cudaGetSymbolAddress((void**)&idxS, g_idxS);

    cudaFuncSetAttribute(k_gemm_fused, cudaFuncAttributeMaxDynamicSharedMemorySize, GEMM_SMEM);

    // ---- prep ----
    cudaMemsetAsync(cntS, 0, sizeof(int) * NSP);
    cudaMemsetAsync(cntR, 0, sizeof(int) * NRX);
    k_build<<<(NED + 255) / 256, 256>>>(edge_species, edge_reaction);
    k_init<<<IBS + IBR + 512, 256>>>(species_indices, is_external, species_table,
                                     external_table, prop_type_ids, prop_params,
                                     type_table, W_param, b_param, Wr, Ws, hsA, hrA);

    const size_t WSZ = (size_t)128 * 256;
    const __half* Wr0 = wt + 0 * WSZ;
    const __half* Ws0 = wt + 1 * WSZ;
    const __half* Wr1 = wt + 2 * WSZ;
    const __half* Ws1 = wt + 3 * WSZ;
    const size_t HRB = sizeof(__half) * (size_t)NRX * DM;
    const size_t HSB = sizeof(__half) * (size_t)NSP * DM;

    // ---- layer 0 ----
    cudaMemsetAsync(hrB, 0, HRB);
    k_gemm_fused<<<GEMM_GRID, 512, GEMM_SMEM>>>(
        hsA, Wr0, NSP, 128, 0, cntS, idxS, CAP_S, hrB,
        hrA, Wr0, NRX, 0,   0, br, hrB);
    cudaMemsetAsync(hsB, 0, HSB);
    k_gemm_fused<<<GEMM_GRID, 512, GEMM_SMEM>>>(
        hrB, Ws0, NRX, 128, 1, cntR, idxR, CAP_R, hsB,
        hsA, Ws0, NSP, 0,   0, bs, hsB);

    // ---- layer 1 ----
    cudaMemsetAsync(hrA, 0, HRB);
    k_gemm_fused<<<GEMM_GRID, 512, GEMM_SMEM>>>(
        hsB, Wr1, NSP, 128, 1, cntS, idxS, CAP_S, hrA,
        hrB, Wr1, NRX, 0,   1, br + DM, hrA);
    cudaMemsetAsync(hsA, 0, HSB);
    k_gemm_fused<<<GEMM_GRID, 512, GEMM_SMEM>>>(
        hrA, Ws1, NRX, 128, 1, cntR, idxR, CAP_R, hsA,
        hsB, Ws1, NSP, 0,   1, bs + DM, hsA);

    k_pool<<<dim3(2, BGR, 2), 256>>>(hsA, hrA, out);
}

// round 16
// speedup vs baseline: 1.5220x; 1.5220x over previous
#include <cuda_runtime.h>
#include <cuda_fp16.h>
#include <cstdint>

#define NSP 100000
#define NRX 200000
#define NED 1000000
#define DM  128
#define BGR 50
#define NS_PER 2000
#define NR_PER 4000
#define CAP_R 32        // per-reaction list capacity (deg lambda = 5)
#define CAP_S 64        // per-species list capacity (deg lambda = 10)

// State / message buffers — all fp16
__device__ __half g_hsA[NSP * DM];
__device__ __half g_hsB[NSP * DM];
__device__ __half g_hrA[NRX * DM];
__device__ __half g_hrB[NRX * DM];
__device__ __half g_y[NSP * DM];
__device__ __half g_z[NRX * DM];
// Pre-transposed fp16 weights: [which of 4][n=128][k=256]
__device__ __half g_wt[4][128 * 256];
// Adjacency (built per launch)
__device__ int g_cntR[NRX];
__device__ int g_cntS[NSP];
__device__ int g_idxR[(size_t)NRX * CAP_R];
__device__ int g_idxS[(size_t)NSP * CAP_S];

// ---------------------------------------------------------------------------
__device__ __forceinline__ uint32_t smem_u32(const void* p) {
    uint32_t a;
    asm("{ .reg .u64 t; cvta.to.shared.u64 t, %1; cvt.u32.u64 %0, t; }" : "=r"(a) : "l"(p));
    return a;
}
__device__ __forceinline__ void ldsm4(uint32_t r[4], uint32_t addr) {
    asm volatile("ldmatrix.sync.aligned.m8n8.x4.shared.b16 {%0,%1,%2,%3}, [%4];"
                 : "=r"(r[0]), "=r"(r[1]), "=r"(r[2]), "=r"(r[3]) : "r"(addr));
}
__device__ __forceinline__ void mma16816(float c[4], const uint32_t a[4],
                                         uint32_t b0, uint32_t b1) {
    asm volatile(
        "mma.sync.aligned.m16n8k16.row.col.f32.f16.f16.f32 "
        "{%0,%1,%2,%3}, {%4,%5,%6,%7}, {%8,%9}, {%0,%1,%2,%3};"
        : "+f"(c[0]), "+f"(c[1]), "+f"(c[2]), "+f"(c[3])
        : "r"(a[0]), "r"(a[1]), "r"(a[2]), "r"(a[3]), "r"(b0), "r"(b1));
}
__device__ __forceinline__ void cpa16(uint32_t smem, const void* gmem, uint32_t bytes) {
    asm volatile("cp.async.ca.shared.global [%0], [%1], 16, %2;"
                 :: "r"(smem), "l"(gmem), "r"(bytes) : "memory");
}

// ---------------------------------------------------------------------------
// Adjacency build: one pass over edges, slot placement via atomicAdd.
__global__ void k_build(const int* __restrict__ es, const int* __restrict__ ed) {
    int e = blockIdx.x * blockDim.x + threadIdx.x;
    if (e >= NED) return;
    int s = es[e], d = ed[e];
    int slotR = atomicAdd(&g_cntR[d], 1);
    if (slotR < CAP_R) g_idxR[(size_t)d * CAP_R + slotR] = s;
    int slotS = atomicAdd(&g_cntS[s], 1);
    if (slotS < CAP_S) g_idxS[(size_t)s * CAP_S + slotS] = d;
}

// ---------------------------------------------------------------------------
// Fused init + weight prep.
#define IBS ((NSP * 32 + 255) / 256)
#define IBR ((NRX * 32 + 255) / 256)
__global__ void k_init(const int* __restrict__ sidx, const int* __restrict__ ext,
                       const float* __restrict__ st, const float* __restrict__ et,
                       const int* __restrict__ tids, const float* __restrict__ params,
                       const float* __restrict__ tt, const float* __restrict__ Wp,
                       const float* __restrict__ bp,
                       const float* __restrict__ Wr, const float* __restrict__ Ws,
                       __half* __restrict__ hs, __half* __restrict__ hr) {
    if ((int)blockIdx.x < IBS) {
        int t = blockIdx.x * blockDim.x + threadIdx.x;
        int row = t >> 5, c = t & 31;
        if (row >= NSP) return;
        int si = sidx[row], ei = ext[row];
        float4 a = ((const float4*)st)[si * 32 + c];
        float4 b = ((const float4*)et)[ei * 32 + c];
        __half2 o01 = __floats2half2_rn(a.x + b.x, a.y + b.y);
        __half2 o23 = __floats2half2_rn(a.z + b.z, a.w + b.w);
        uint2 o;
        o.x = *(uint32_t*)&o01; o.y = *(uint32_t*)&o23;
        ((uint2*)hs)[row * 32 + c] = o;
    } else if ((int)blockIdx.x < IBS + IBR) {
        int t = ((int)blockIdx.x - IBS) * blockDim.x + threadIdx.x;
        int row = t >> 5, c = t & 31;
        if (row >= NRX) return;
        int ti = tids[row];
        float4 acc = ((const float4*)tt)[ti * 32 + c];
        float4 bb  = ((const float4*)bp)[c];
        acc.x += bb.x; acc.y += bb.y; acc.z += bb.z; acc.w += bb.w;
#pragma unroll
        for (int k = 0; k < 8; k++) {
            float p = params[row * 8 + k];
            float4 w = ((const float4*)Wp)[k * 32 + c];
            acc.x += p * w.x; acc.y += p * w.y; acc.z += p * w.z; acc.w += p * w.w;
        }
        __half2 o01 = __floats2half2_rn(acc.x, acc.y);
        __half2 o23 = __floats2half2_rn(acc.z, acc.w);
        uint2 o;
        o.x = *(uint32_t*)&o01; o.y = *(uint32_t*)&o23;
        ((uint2*)hr)[row * 32 + c] = o;
    } else {
        int idx = ((int)blockIdx.x - IBS - IBR) * blockDim.x + threadIdx.x;
        if (idx >= 4 * 256 * 128) return;
        int l = idx >> 15;
        int rem = idx & 32767;
        int k = rem >> 7, n = rem & 127;
        const float* src = (l & 1) ? (Ws + (size_t)(l >> 1) * 2 * DM * DM)
                                   : (Wr + (size_t)(l >> 1) * 2 * DM * DM);
        g_wt[l][n * 256 + k] = __float2half(src[k * DM + n]);
    }
}

// ---------------------------------------------------------------------------
// CSR gather segsum: dst[w] += sum_{i<deg} src[idx[w][i]]   (owned write,
// fp32 accumulation, MLP-8: 8 indices prefetched via int4, 8 gathers in flight).
__global__ void k_gather(const __half* __restrict__ src, __half* __restrict__ dst,
                         const int* __restrict__ cnt, const int* __restrict__ idx,
                         int cap, int n) {
    int t = blockIdx.x * blockDim.x + threadIdx.x;
    int w = t >> 5, lane = t & 31;
    if (w >= n) return;
    int deg = cnt[w];
    if (deg > cap) deg = cap;
    if (deg == 0) return;
    const int* lst = idx + (size_t)w * cap;
    float ax = 0.f, ay = 0.f, az = 0.f, aw = 0.f;
    for (int i = 0; i < deg; i += 8) {
        int4 a = *(const int4*)(lst + i);
        int4 b = *(const int4*)(lst + i + 4);
        int id[8] = {a.x, a.y, a.z, a.w, b.x, b.y, b.z, b.w};
        uint2 g[8];
#pragma unroll
        for (int j = 0; j < 8; j++) {
            g[j] = make_uint2(0u, 0u);
            if (i + j < deg)
                g[j] = ((const uint2*)(src + (size_t)id[j] * DM))[lane];
        }
#pragma unroll
        for (int j = 0; j < 8; j++) {
            float2 f0 = __half22float2(*(__half2*)&g[j].x);
            float2 f1 = __half22float2(*(__half2*)&g[j].y);
            ax += f0.x; ay += f0.y; az += f1.x; aw += f1.y;
        }
    }
    uint2 st = ((uint2*)(dst + (size_t)w * DM))[lane];
    float2 s0 = __half22float2(*(__half2*)&st.x);
    float2 s1 = __half22float2(*(__half2*)&st.y);
    __half2 o0 = __floats2half2_rn(ax + s0.x, ay + s0.y);
    __half2 o1 = __floats2half2_rn(az + s1.x, aw + s1.y);
    uint2 o;
    o.x = *(uint32_t*)&o0; o.y = *(uint32_t*)&o1;
    ((uint2*)(dst + (size_t)w * DM))[lane] = o;
}

// ---------------------------------------------------------------------------
// Persistent paired GEMM, B fragments in registers (R14-proven).
#define PITCH2 136
#define PB2    (PITCH2 * 2)
#define TILE2  (128 * PB2)         // 34816 B
#define GEMM_GRID 148

__global__ void __launch_bounds__(512, 1) k_gemm_pp(
    __half* __restrict__ DA, const __half* __restrict__ XA,
    const __half* __restrict__ WtA, int nA, int koffA, int reluA,
    __half* __restrict__ DB, const __half* __restrict__ XB,
    const __half* __restrict__ WtB, const float* __restrict__ biasB,
    int nB, int koffB, int reluB)
{
    extern __shared__ char sm[];
    uint32_t aW  = smem_u32(sm);
    uint32_t aX0 = aW + TILE2;
    uint32_t aX1 = aX0 + TILE2;

    int G = gridDim.x;
    int tA = (nA + 127) >> 7, tB = (nB + 127) >> 7;
    int cA = (int)(((long long)G * tA) / (tA + tB));
    if (tA > 0 && cA == 0) cA = 1;
    if (tB > 0 && cA == G) cA = G - 1;

    const bool jobB = ((int)blockIdx.x >= cA);
    const __half* X  = jobB ? XB : XA;
    const __half* Wt = jobB ? WtB : WtA;
    const int n      = jobB ? nB : nA;
    const int koff   = jobB ? koffB : koffA;
    const int relu   = jobB ? reluB : reluA;
    const int nT     = jobB ? tB : tA;
    const int tile0  = jobB ? ((int)blockIdx.x - cA) : (int)blockIdx.x;
    const int stride = jobB ? (G - cA) : cA;
    __half* D = jobB ? DB : DA;

    int tid = threadIdx.x;
    int lane = tid & 31, wid = tid >> 5;
    int wm = (wid & 3) * 32;
    int wn = (wid >> 2) * 32;

    // ---- W tile -> smem (one-time) ----
#pragma unroll
    for (int i = 0; i < 4; i++) {
        int f = i * 512 + tid;
        int r = f >> 4, c = f & 15;
        cpa16(aW + (uint32_t)r * PB2 + c * 16,
              Wt + (size_t)r * 256 + koff + c * 8, 16u);
    }
    asm volatile("cp.async.commit_group;" ::: "memory");

    bool active = (tile0 < nT);

    if (active) {
        int rb = tile0 * 128;
#pragma unroll
        for (int i = 0; i < 4; i++) {
            int f = i * 512 + tid;
            int r = f >> 4, c = f & 15;
            int gr = rb + r;
            const __half* gp = X + (size_t)(gr < n ? gr : 0) * DM + c * 8;
            cpa16(aX0 + (uint32_t)r * PB2 + c * 16, gp, (gr < n) ? 16u : 0u);
        }
    }
    asm volatile("cp.async.commit_group;" ::: "memory");
    asm volatile("cp.async.wait_group 1;" ::: "memory");
    __syncthreads();

    // ---- hoist B fragments ----
    uint32_t bOff = (uint32_t)(wn + (lane & 7) + ((lane >> 4) & 1) * 8) * PB2
                  + (((lane >> 3) & 1) * 8) * 2;
    uint32_t bF[8][8];
#pragma unroll
    for (int ks = 0; ks < 8; ks++)
#pragma unroll
        for (int q = 0; q < 2; q++)
            ldsm4(&bF[ks][q * 4], aW + bOff + ks * 32 + q * 16 * PB2);

    if (!active) {
        asm volatile("cp.async.wait_group 0;" ::: "memory");
        return;
    }

    uint32_t aOff = (uint32_t)(wm + (lane & 15)) * PB2 + ((lane >> 4) * 8) * 2;
    const __half2 z2 = __float2half2_rn(0.f);

    int t = tile0, buf = 0;
    while (t < nT) {
        int tn = t + stride;
        if (tn < nT) {
            uint32_t aXn = buf ? aX0 : aX1;
            int rb = tn * 128;
#pragma unroll
            for (int i = 0; i < 4; i++) {
                int f = i * 512 + tid;
                int r = f >> 4, c = f & 15;
                int gr = rb + r;
                const __half* gp = X + (size_t)(gr < n ? gr : 0) * DM + c * 8;
                cpa16(aXn + (uint32_t)r * PB2 + c * 16, gp, (gr < n) ? 16u : 0u);
            }
            asm volatile("cp.async.commit_group;" ::: "memory");
            asm volatile("cp.async.wait_group 1;" ::: "memory");
        } else {
            asm volatile("cp.async.wait_group 0;" ::: "memory");
        }
        __syncthreads();

        uint32_t aX = buf ? aX1 : aX0;
        float acc[2][4][4];
#pragma unroll
        for (int mt = 0; mt < 2; mt++)
#pragma unroll
            for (int nt = 0; nt < 4; nt++)
#pragma unroll
                for (int j = 0; j < 4; j++) acc[mt][nt][j] = 0.f;

#pragma unroll
        for (int ks = 0; ks < 8; ks++) {
            uint32_t aF[2][4];
            ldsm4(aF[0], aX + aOff + ks * 32);
            ldsm4(aF[1], aX + aOff + ks * 32 + 16 * PB2);
            if (relu) {
#pragma unroll
                for (int mt = 0; mt < 2; mt++)
#pragma unroll
                    for (int j = 0; j < 4; j++) {
                        __half2 h = __hmax2(*(__half2*)&aF[mt][j], z2);
                        aF[mt][j] = *(uint32_t*)&h;
                    }
            }
#pragma unroll
            for (int mt = 0; mt < 2; mt++)
#pragma unroll
                for (int q = 0; q < 2; q++) {
                    mma16816(acc[mt][q * 2 + 0], aF[mt], bF[ks][q * 4 + 0], bF[ks][q * 4 + 1]);
                    mma16816(acc[mt][q * 2 + 1], aF[mt], bF[ks][q * 4 + 2], bF[ks][q * 4 + 3]);
                }
        }

        int r0 = (lane >> 2);
        int c0 = (lane & 3) * 2;
        int rowBase = t * 128;
#pragma unroll
        for (int mt = 0; mt < 2; mt++) {
#pragma unroll
            for (int nt = 0; nt < 4; nt++) {
                int col = wn + nt * 8 + c0;
                float2 b2 = make_float2(0.f, 0.f);
                if (jobB) b2 = *(const float2*)&biasB[col];
                int rowA = rowBase + wm + mt * 16 + r0;
                int rowB = rowA + 8;
                if (rowA < n)
                    *(__half2*)&D[(size_t)rowA * DM + col] =
                        __floats2half2_rn(acc[mt][nt][0] + b2.x, acc[mt][nt][1] + b2.y);
                if (rowB < n)
                    *(__half2*)&D[(size_t)rowB * DM + col] =
                        __floats2half2_rn(acc[mt][nt][2] + b2.x, acc[mt][nt][3] + b2.y);
            }
        }
        __syncthreads();
        t = tn;
        buf ^= 1;
    }
}

// ---------------------------------------------------------------------------
// Pool: fp16 states, relu on load, fp32 accumulation.
__global__ void k_pool(const __half* __restrict__ hs, const __half* __restrict__ hr,
                       float* __restrict__ out) {
    int kind = blockIdx.z;
    int b = blockIdx.y;
    int lane = threadIdx.x & 31;
    int g = threadIdx.x >> 5;
    int col2 = blockIdx.x * 32 + lane;
    const __half* h = kind ? hr : hs;
    int np = kind ? NR_PER : NS_PER;
    float inv = kind ? (1.f / NR_PER) : (1.f / NS_PER);
    size_t base2 = (size_t)b * np * 64;
    const __half2* h2 = (const __half2*)h;
    float sx = 0.f, sy = 0.f;
    for (int i = g; i < np; i += 8) {
        float2 f = __half22float2(h2[base2 + (size_t)i * 64 + col2]);
        sx += fmaxf(f.x, 0.f);
        sy += fmaxf(f.y, 0.f);
    }
    __shared__ float red[8][64];
    red[g][lane * 2]     = sx;
    red[g][lane * 2 + 1] = sy;
    __syncthreads();
    if (g == 0) {
        float tx = 0.f, ty = 0.f;
#pragma unroll
        for (int j = 0; j < 8; j++) { tx += red[j][lane * 2]; ty += red[j][lane * 2 + 1]; }
        int col = col2 * 2;
        out[b * 256 + kind * 128 + col]     = tx * inv;
        out[b * 256 + kind * 128 + col + 1] = ty * inv;
    }
}

// ---------------------------------------------------------------------------
extern "C" void kernel_launch(void* const* d_in, const int* in_sizes, int n_in,
                              void* d_out, int out_size) {
    const int*   species_indices = (const int*)  d_in[0];
    const int*   is_external     = (const int*)  d_in[1];
    const int*   prop_type_ids   = (const int*)  d_in[2];
    const float* prop_params     = (const float*)d_in[3];
    const int*   edge_species    = (const int*)  d_in[4];
    const int*   edge_reaction   = (const int*)  d_in[5];
    const float* species_table   = (const float*)d_in[8];
    const float* external_table  = (const float*)d_in[9];
    const float* type_table      = (const float*)d_in[10];
    const float* W_param         = (const float*)d_in[11];
    const float* b_param         = (const float*)d_in[12];
    const float* Wr              = (const float*)d_in[13];
    const float* br              = (const float*)d_in[14];
    const float* Ws              = (const float*)d_in[15];
    const float* bs              = (const float*)d_in[16];
    float* out = (float*)d_out;

    __half *hsA, *hsB, *hrA, *hrB, *wt;
    int *cntR, *cntS, *idxR, *idxS;
    cudaGetSymbolAddress((void**)&hsA, g_hsA);
    cudaGetSymbolAddress((void**)&hsB, g_hsB);
    cudaGetSymbolAddress((void**)&hrA, g_hrA);
    cudaGetSymbolAddress((void**)&hrB, g_hrB);
    cudaGetSymbolAddress((void**)&wt, g_wt);
    cudaGetSymbolAddress((void**)&cntR, g_cntR);
    cudaGetSymbolAddress((void**)&cntS, g_cntS);
    cudaGetSymbolAddress((void**)&idxR, g_idxR);
    cudaGetSymbolAddress((void**)&idxS, g_idxS);

    const int GEMM_SMEM = 3 * TILE2;   // 104448 B
    cudaFuncSetAttribute(k_gemm_pp, cudaFuncAttributeMaxDynamicSharedMemorySize, GEMM_SMEM);

    // ---- prep: adjacency + embeddings + weights ----
    cudaMemsetAsync(cntR, 0, sizeof(int) * NRX);
    cudaMemsetAsync(cntS, 0, sizeof(int) * NSP);
    k_build<<<(NED + 255) / 256, 256>>>(edge_species, edge_reaction);
    k_init<<<IBS + IBR + 512, 256>>>(species_indices, is_external, species_table,
                                     external_table, prop_type_ids, prop_params,
                                     type_table, W_param, b_param, Wr, Ws, hsA, hrA);

    const size_t WSZ = (size_t)128 * 256;
    const __half* Wr0 = wt + 0 * WSZ;
    const __half* Ws0 = wt + 1 * WSZ;
    const __half* Wr1 = wt + 2 * WSZ;
    const __half* Ws1 = wt + 3 * WSZ;
    __half* y = (__half*)g_y;  // via symbol below
    __half* z;
    cudaGetSymbolAddress((void**)&y, g_y);
    cudaGetSymbolAddress((void**)&z, g_z);

    const int gbR = (NRX * 32 + 255) / 256;   // gather: warp per dst row
    const int gbS = (NSP * 32 + 255) / 256;

    // ---- layer 0 (inputs raw) ----
    k_gemm_pp<<<GEMM_GRID, 512, GEMM_SMEM>>>(
        y,   hsA, Wr0, NSP, 128, 0,
        hrB, hrA, Wr0, br,  NRX, 0, 0);
    k_gather<<<gbR, 256>>>(y, hrB, cntR, idxR, CAP_R, NRX);
    k_gemm_pp<<<GEMM_GRID, 512, GEMM_SMEM>>>(
        z,   hrB, Ws0, NRX, 128, 1,
        hsB, hsA, Ws0, bs,  NSP, 0, 0);
    k_gather<<<gbS, 256>>>(z, hsB, cntS, idxS, CAP_S, NSP);

    // ---- layer 1 (inputs need relu) ----
    k_gemm_pp<<<GEMM_GRID, 512, GEMM_SMEM>>>(
        y,   hsB, Wr1, NSP, 128, 1,
        hrA, hrB, Wr1, br + DM, NRX, 0, 1);
    k_gather<<<gbR, 256>>>(y, hrA, cntR, idxR, CAP_R, NRX);
    k_gemm_pp<<<GEMM_GRID, 512, GEMM_SMEM>>>(
        z,   hrA, Ws1, NRX, 128, 1,
        hsA, hsB, Ws1, bs + DM, NSP, 0, 1);
    k_gather<<<gbS, 256>>>(z, hsA, cntS, idxS, CAP_S, NSP);

    k_pool<<<dim3(2, BGR, 2), 256>>>(hsA, hrA, out);
}

// round 17
// speedup vs baseline: 1.7315x; 1.1376x over previous
#include <cuda_runtime.h>
#include <cuda_fp16.h>
#include <cstdint>

#define NSP 100000
#define NRX 200000
#define NED 1000000
#define DM  128
#define BGR 50
#define NS_PER 2000
#define NR_PER 4000

// State / message buffers — all fp16
__device__ __half g_hsA[NSP * DM];
__device__ __half g_hsB[NSP * DM];
__device__ __half g_hrA[NRX * DM];
__device__ __half g_hrB[NRX * DM];
__device__ __half g_y[NSP * DM];
__device__ __half g_z[NRX * DM];
// Pre-transposed fp16 weights: [which of 4][n=128][k=256]
__device__ __half g_wt[4][128 * 256];

// ---------------------------------------------------------------------------
__device__ __forceinline__ uint32_t smem_u32(const void* p) {
    uint32_t a;
    asm("{ .reg .u64 t; cvta.to.shared.u64 t, %1; cvt.u32.u64 %0, t; }" : "=r"(a) : "l"(p));
    return a;
}
__device__ __forceinline__ void ldsm4(uint32_t r[4], uint32_t addr) {
    asm volatile("ldmatrix.sync.aligned.m8n8.x4.shared.b16 {%0,%1,%2,%3}, [%4];"
                 : "=r"(r[0]), "=r"(r[1]), "=r"(r[2]), "=r"(r[3]) : "r"(addr));
}
__device__ __forceinline__ void mma16816(float c[4], const uint32_t a[4],
                                         uint32_t b0, uint32_t b1) {
    asm volatile(
        "mma.sync.aligned.m16n8k16.row.col.f32.f16.f16.f32 "
        "{%0,%1,%2,%3}, {%4,%5,%6,%7}, {%8,%9}, {%0,%1,%2,%3};"
        : "+f"(c[0]), "+f"(c[1]), "+f"(c[2]), "+f"(c[3])
        : "r"(a[0]), "r"(a[1]), "r"(a[2]), "r"(a[3]), "r"(b0), "r"(b1));
}
__device__ __forceinline__ void cpa16(uint32_t smem, const void* gmem, uint32_t bytes) {
    asm volatile("cp.async.ca.shared.global [%0], [%1], 16, %2;"
                 :: "r"(smem), "l"(gmem), "r"(bytes) : "memory");
}

// ---------------------------------------------------------------------------
// Fused init + weight prep.
#define IBS ((NSP * 32 + 255) / 256)
#define IBR ((NRX * 32 + 255) / 256)
__global__ void k_init(const int* __restrict__ sidx, const int* __restrict__ ext,
                       const float* __restrict__ st, const float* __restrict__ et,
                       const int* __restrict__ tids, const float* __restrict__ params,
                       const float* __restrict__ tt, const float* __restrict__ Wp,
                       const float* __restrict__ bp,
                       const float* __restrict__ Wr, const float* __restrict__ Ws,
                       __half* __restrict__ hs, __half* __restrict__ hr) {
    if ((int)blockIdx.x < IBS) {
        int t = blockIdx.x * blockDim.x + threadIdx.x;
        int row = t >> 5, c = t & 31;
        if (row >= NSP) return;
        int si = sidx[row], ei = ext[row];
        float4 a = ((const float4*)st)[si * 32 + c];
        float4 b = ((const float4*)et)[ei * 32 + c];
        __half2 o01 = __floats2half2_rn(a.x + b.x, a.y + b.y);
        __half2 o23 = __floats2half2_rn(a.z + b.z, a.w + b.w);
        uint2 o;
        o.x = *(uint32_t*)&o01; o.y = *(uint32_t*)&o23;
        ((uint2*)hs)[row * 32 + c] = o;
    } else if ((int)blockIdx.x < IBS + IBR) {
        int t = ((int)blockIdx.x - IBS) * blockDim.x + threadIdx.x;
        int row = t >> 5, c = t & 31;
        if (row >= NRX) return;
        int ti = tids[row];
        float4 acc = ((const float4*)tt)[ti * 32 + c];
        float4 bb  = ((const float4*)bp)[c];
        acc.x += bb.x; acc.y += bb.y; acc.z += bb.z; acc.w += bb.w;
#pragma unroll
        for (int k = 0; k < 8; k++) {
            float p = params[row * 8 + k];
            float4 w = ((const float4*)Wp)[k * 32 + c];
            acc.x += p * w.x; acc.y += p * w.y; acc.z += p * w.z; acc.w += p * w.w;
        }
        __half2 o01 = __floats2half2_rn(acc.x, acc.y);
        __half2 o23 = __floats2half2_rn(acc.z, acc.w);
        uint2 o;
        o.x = *(uint32_t*)&o01; o.y = *(uint32_t*)&o23;
        ((uint2*)hr)[row * 32 + c] = o;
    } else {
        int idx = ((int)blockIdx.x - IBS - IBR) * blockDim.x + threadIdx.x;
        if (idx >= 4 * 256 * 128) return;
        int l = idx >> 15;
        int rem = idx & 32767;
        int k = rem >> 7, n = rem & 127;
        const float* src = (l & 1) ? (Ws + (size_t)(l >> 1) * 2 * DM * DM)
                                   : (Wr + (size_t)(l >> 1) * 2 * DM * DM);
        g_wt[l][n * 256 + k] = __float2half(src[k * DM + n]);
    }
}

// ---------------------------------------------------------------------------
// Segment sum, 8 edges per warp, fp16 rows, v2.f16x2 vector RED (proven best).
__global__ void k_seg8(const __half* __restrict__ src, __half* __restrict__ dst,
                       const int* __restrict__ es, const int* __restrict__ ed) {
    int t = blockIdx.x * blockDim.x + threadIdx.x;
    int w = t >> 5, lane = t & 31;
    int e0 = w * 8;
    if (e0 >= NED) return;
    int4 sa = *(const int4*)(es + e0);
    int4 sb = *(const int4*)(es + e0 + 4);
    int4 da = *(const int4*)(ed + e0);
    int4 db = *(const int4*)(ed + e0 + 4);
    int sI[8] = {sa.x, sa.y, sa.z, sa.w, sb.x, sb.y, sb.z, sb.w};
    int dI[8] = {da.x, da.y, da.z, da.w, db.x, db.y, db.z, db.w};
    uint2 v[8];
#pragma unroll
    for (int i = 0; i < 8; i++)
        v[i] = ((const uint2*)(src + (size_t)sI[i] * DM))[lane];
#pragma unroll
    for (int i = 0; i < 8; i++) {
        __half* p = dst + (size_t)dI[i] * DM + lane * 4;
        asm volatile("red.global.add.noftz.v2.f16x2 [%0], {%1, %2};"
                     :: "l"(p), "r"(v[i].x), "r"(v[i].y) : "memory");
    }
}

// ---------------------------------------------------------------------------
// Persistent paired GEMM, B frags in registers, 3-deep X cp.async pipeline.
// 512 threads (16 warps), warp tile 32x32, CTA tile 128x128, 1 CTA/SM.
#define PITCH2 136
#define PB2    (PITCH2 * 2)
#define TILE2  (128 * PB2)         // 34816 B
#define GEMM_GRID 148
#define NBUF 3

__global__ void __launch_bounds__(512, 1) k_gemm_pp(
    __half* __restrict__ DA, const __half* __restrict__ XA,
    const __half* __restrict__ WtA, int nA, int koffA, int reluA,
    __half* __restrict__ DB, const __half* __restrict__ XB,
    const __half* __restrict__ WtB, const float* __restrict__ biasB,
    int nB, int koffB, int reluB)
{
    extern __shared__ char sm[];
    uint32_t aW  = smem_u32(sm);
    uint32_t aXb = aW + TILE2;       // 3 X buffers follow W

    int G = gridDim.x;
    int tA = (nA + 127) >> 7, tB = (nB + 127) >> 7;
    int cA = (int)(((long long)G * tA) / (tA + tB));
    if (tA > 0 && cA == 0) cA = 1;
    if (tB > 0 && cA == G) cA = G - 1;

    const bool jobB = ((int)blockIdx.x >= cA);
    const __half* X  = jobB ? XB : XA;
    const __half* Wt = jobB ? WtB : WtA;
    const int n      = jobB ? nB : nA;
    const int koff   = jobB ? koffB : koffA;
    const int relu   = jobB ? reluB : reluA;
    const int nT     = jobB ? tB : tA;
    const int tile0  = jobB ? ((int)blockIdx.x - cA) : (int)blockIdx.x;
    const int stride = jobB ? (G - cA) : cA;
    __half* D = jobB ? DB : DA;

    int tid = threadIdx.x;
    int lane = tid & 31, wid = tid >> 5;
    int wm = (wid & 3) * 32;
    int wn = (wid >> 2) * 32;

    // ---- W tile -> smem (group 0) ----
#pragma unroll
    for (int i = 0; i < 4; i++) {
        int f = i * 512 + tid;
        int r = f >> 4, c = f & 15;
        cpa16(aW + (uint32_t)r * PB2 + c * 16,
              Wt + (size_t)r * 256 + koff + c * 8, 16u);
    }
    asm volatile("cp.async.commit_group;" ::: "memory");

    bool active = (tile0 < nT);

    // ---- prologue: issue X for tiles tile0, +s, +2s into bufs 0,1,2 ----
#pragma unroll
    for (int pb = 0; pb < NBUF; pb++) {
        int tt = tile0 + pb * stride;
        if (active && tt < nT) {
            uint32_t aX = aXb + pb * TILE2;
            int rb = tt * 128;
#pragma unroll
            for (int i = 0; i < 4; i++) {
                int f = i * 512 + tid;
                int r = f >> 4, c = f & 15;
                int gr = rb + r;
                const __half* gp = X + (size_t)(gr < n ? gr : 0) * DM + c * 8;
                cpa16(aX + (uint32_t)r * PB2 + c * 16, gp, (gr < n) ? 16u : 0u);
            }
        }
        asm volatile("cp.async.commit_group;" ::: "memory");
    }

    // W complete (3 X groups may still be pending)
    asm volatile("cp.async.wait_group 3;" ::: "memory");
    __syncthreads();

    // ---- hoist B fragments ----
    uint32_t bOff = (uint32_t)(wn + (lane & 7) + ((lane >> 4) & 1) * 8) * PB2
                  + (((lane >> 3) & 1) * 8) * 2;
    uint32_t bF[8][8];
#pragma unroll
    for (int ks = 0; ks < 8; ks++)
#pragma unroll
        for (int q = 0; q < 2; q++)
            ldsm4(&bF[ks][q * 4], aW + bOff + ks * 32 + q * 16 * PB2);

    if (!active) {
        asm volatile("cp.async.wait_group 0;" ::: "memory");
        return;
    }

    uint32_t aOff = (uint32_t)(wm + (lane & 15)) * PB2 + ((lane >> 4) * 8) * 2;
    const __half2 z2 = __float2half2_rn(0.f);

    int t = tile0, idx = 0;
    while (t < nT) {
        // oldest X group complete (keep 2 newer in flight)
        asm volatile("cp.async.wait_group 2;" ::: "memory");
        __syncthreads();

        uint32_t aX = aXb + idx * TILE2;
        float acc[2][4][4];
#pragma unroll
        for (int mt = 0; mt < 2; mt++)
#pragma unroll
            for (int nt = 0; nt < 4; nt++)
#pragma unroll
                for (int j = 0; j < 4; j++) acc[mt][nt][j] = 0.f;

#pragma unroll
        for (int ks = 0; ks < 8; ks++) {
            uint32_t aF[2][4];
            ldsm4(aF[0], aX + aOff + ks * 32);
            ldsm4(aF[1], aX + aOff + ks * 32 + 16 * PB2);
            if (relu) {
#pragma unroll
                for (int mt = 0; mt < 2; mt++)
#pragma unroll
                    for (int j = 0; j < 4; j++) {
                        __half2 h = __hmax2(*(__half2*)&aF[mt][j], z2);
                        aF[mt][j] = *(uint32_t*)&h;
                    }
            }
#pragma unroll
            for (int mt = 0; mt < 2; mt++)
#pragma unroll
                for (int q = 0; q < 2; q++) {
                    mma16816(acc[mt][q * 2 + 0], aF[mt], bF[ks][q * 4 + 0], bF[ks][q * 4 + 1]);
                    mma16816(acc[mt][q * 2 + 1], aF[mt], bF[ks][q * 4 + 2], bF[ks][q * 4 + 3]);
                }
        }

        // ---- epilogue ----
        int r0 = (lane >> 2);
        int c0 = (lane & 3) * 2;
        int rowBase = t * 128;
#pragma unroll
        for (int mt = 0; mt < 2; mt++) {
#pragma unroll
            for (int nt = 0; nt < 4; nt++) {
                int col = wn + nt * 8 + c0;
                float2 b2 = make_float2(0.f, 0.f);
                if (jobB) b2 = *(const float2*)&biasB[col];
                int rowA = rowBase + wm + mt * 16 + r0;
                int rowB = rowA + 8;
                if (rowA < n)
                    *(__half2*)&D[(size_t)rowA * DM + col] =
                        __floats2half2_rn(acc[mt][nt][0] + b2.x, acc[mt][nt][1] + b2.y);
                if (rowB < n)
                    *(__half2*)&D[(size_t)rowB * DM + col] =
                        __floats2half2_rn(acc[mt][nt][2] + b2.x, acc[mt][nt][3] + b2.y);
            }
        }
        __syncthreads();   // all reads of this buffer done before refill

        // ---- issue X for tile t + 3*stride into the freed buffer ----
        int tIss = t + NBUF * stride;
        if (tIss < nT) {
            int rb = tIss * 128;
#pragma unroll
            for (int i = 0; i < 4; i++) {
                int f = i * 512 + tid;
                int r = f >> 4, c = f & 15;
                int gr = rb + r;
                const __half* gp = X + (size_t)(gr < n ? gr : 0) * DM + c * 8;
                cpa16(aX + (uint32_t)r * PB2 + c * 16, gp, (gr < n) ? 16u : 0u);
            }
        }
        asm volatile("cp.async.commit_group;" ::: "memory");  // possibly empty group

        t += stride;
        idx = (idx + 1) % NBUF;
    }
    asm volatile("cp.async.wait_group 0;" ::: "memory");
}

// ---------------------------------------------------------------------------
// Pool: fp16 states, relu on load, fp32 accumulation.
__global__ void k_pool(const __half* __restrict__ hs, const __half* __restrict__ hr,
                       float* __restrict__ out) {
    int kind = blockIdx.z;
    int b = blockIdx.y;
    int lane = threadIdx.x & 31;
    int g = threadIdx.x >> 5;
    int col2 = blockIdx.x * 32 + lane;
    const __half* h = kind ? hr : hs;
    int np = kind ? NR_PER : NS_PER;
    float inv = kind ? (1.f / NR_PER) : (1.f / NS_PER);
    size_t base2 = (size_t)b * np * 64;
    const __half2* h2 = (const __half2*)h;
    float sx = 0.f, sy = 0.f;
    for (int i = g; i < np; i += 8) {
        float2 f = __half22float2(h2[base2 + (size_t)i * 64 + col2]);
        sx += fmaxf(f.x, 0.f);
        sy += fmaxf(f.y, 0.f);
    }
    __shared__ float red[8][64];
    red[g][lane * 2]     = sx;
    red[g][lane * 2 + 1] = sy;
    __syncthreads();
    if (g == 0) {
        float tx = 0.f, ty = 0.f;
#pragma unroll
        for (int j = 0; j < 8; j++) { tx += red[j][lane * 2]; ty += red[j][lane * 2 + 1]; }
        int col = col2 * 2;
        out[b * 256 + kind * 128 + col]     = tx * inv;
        out[b * 256 + kind * 128 + col + 1] = ty * inv;
    }
}

// ---------------------------------------------------------------------------
extern "C" void kernel_launch(void* const* d_in, const int* in_sizes, int n_in,
                              void* d_out, int out_size) {
    const int*   species_indices = (const int*)  d_in[0];
    const int*   is_external     = (const int*)  d_in[1];
    const int*   prop_type_ids   = (const int*)  d_in[2];
    const float* prop_params     = (const float*)d_in[3];
    const int*   edge_species    = (const int*)  d_in[4];
    const int*   edge_reaction   = (const int*)  d_in[5];
    const float* species_table   = (const float*)d_in[8];
    const float* external_table  = (const float*)d_in[9];
    const float* type_table      = (const float*)d_in[10];
    const float* W_param         = (const float*)d_in[11];
    const float* b_param         = (const float*)d_in[12];
    const float* Wr              = (const float*)d_in[13];
    const float* br              = (const float*)d_in[14];
    const float* Ws              = (const float*)d_in[15];
    const float* bs              = (const float*)d_in[16];
    float* out = (float*)d_out;

    __half *hsA, *hsB, *hrA, *hrB, *y, *z, *wt;
    cudaGetSymbolAddress((void**)&hsA, g_hsA);
    cudaGetSymbolAddress((void**)&hsB, g_hsB);
    cudaGetSymbolAddress((void**)&hrA, g_hrA);
    cudaGetSymbolAddress((void**)&hrB, g_hrB);
    cudaGetSymbolAddress((void**)&y, g_y);
    cudaGetSymbolAddress((void**)&z, g_z);
    cudaGetSymbolAddress((void**)&wt, g_wt);

    const int GEMM_SMEM = (1 + NBUF) * TILE2;   // 139264 B
    cudaFuncSetAttribute(k_gemm_pp, cudaFuncAttributeMaxDynamicSharedMemorySize, GEMM_SMEM);

    k_init<<<IBS + IBR + 512, 256>>>(species_indices, is_external, species_table,
                                     external_table, prop_type_ids, prop_params,
                                     type_table, W_param, b_param, Wr, Ws, hsA, hrA);

    const int segBlocks = (NED / 8 * 32) / 256;   // 15625
    const size_t WSZ = (size_t)128 * 256;
    const __half* Wr0 = wt + 0 * WSZ;
    const __half* Ws0 = wt + 1 * WSZ;
    const __half* Wr1 = wt + 2 * WSZ;
    const __half* Ws1 = wt + 3 * WSZ;

    // ---- layer 0 (inputs raw) ----
    k_gemm_pp<<<GEMM_GRID, 512, GEMM_SMEM>>>(
        y,   hsA, Wr0, NSP, 128, 0,
        hrB, hrA, Wr0, br,  NRX, 0, 0);
    k_seg8<<<segBlocks, 256>>>(y, hrB, edge_species, edge_reaction);
    k_gemm_pp<<<GEMM_GRID, 512, GEMM_SMEM>>>(
        z,   hrB, Ws0, NRX, 128, 1,
        hsB, hsA, Ws0, bs,  NSP, 0, 0);
    k_seg8<<<segBlocks, 256>>>(z, hsB, edge_reaction, edge_species);

    // ---- layer 1 (inputs need relu) ----
    k_gemm_pp<<<GEMM_GRID, 512, GEMM_SMEM>>>(
        y,   hsB, Wr1, NSP, 128, 1,
        hrA, hrB, Wr1, br + DM, NRX, 0, 1);
    k_seg8<<<segBlocks, 256>>>(y, hrA, edge_species, edge_reaction);
    k_gemm_pp<<<GEMM_GRID, 512, GEMM_SMEM>>>(
        z,   hrA, Ws1, NRX, 128, 1,
        hsA, hsB, Ws1, bs + DM, NSP, 0, 1);
    k_seg8<<<segBlocks, 256>>>(z, hsA, edge_reaction, edge_species);

    k_pool<<<dim3(2, BGR, 2), 256>>>(hsA, hrA, out);
}